// round 8
// baseline (speedup 1.0000x reference)
#include <cuda_runtime.h>
#include <cstddef>

#define N_NODES 200000
#define N_EDGES 3200000
#define N_GRAPHS 64
#define HID 32
#define HEADS 4

// ---------------- scratch (device globals; no allocation allowed) ----------------
__device__ float g_f[(size_t)N_NODES * HID];      // fc features (both layers)
__device__ float g_el[(size_t)N_NODES * HEADS];   // per-head el (16B/node, float4-loadable)
__device__ float g_er[(size_t)N_NODES * HEADS];
__device__ float g_acc0[(size_t)N_NODES * HID];
__device__ float g_den0[(size_t)N_NODES * HEADS];
__device__ float g_acc1[(size_t)N_NODES * HID];
__device__ float g_den1[(size_t)N_NODES * HEADS];
__device__ float g_sums[N_GRAPHS * HID];
__device__ float g_cnt[N_GRAPHS];

__device__ __forceinline__ void red_add_v4(float* addr, float4 v) {
    asm volatile("red.global.add.v4.f32 [%0], {%1,%2,%3,%4};"
                 :: "l"(addr), "f"(v.x), "f"(v.y), "f"(v.z), "f"(v.w)
                 : "memory");
}

// ---------------- K0: warp-per-node: h = emb[node_ids]; f = h@W0; el/er; zero acc0/den0 ----------------
__global__ void __launch_bounds__(256) k_gather_fc(
        const int* __restrict__ node_ids,
        const float* __restrict__ emb,
        const float* __restrict__ W,
        const float* __restrict__ al,
        const float* __restrict__ ar) {
    __shared__ float sW[HID * HID];
    int tid = threadIdx.x;
    for (int i = tid; i < HID * HID; i += 256) sW[i] = W[i];
    __syncthreads();

    int t = blockIdx.x * 256 + tid;
    int n = t >> 5;                       // warp per node
    int lane = tid & 31;
    if (n >= N_NODES) return;

    int nid = __ldg(node_ids + n);
    float h = __ldg(emb + (size_t)nid * HID + lane);     // coalesced 128B row
    float f = 0.f;
#pragma unroll
    for (int k = 0; k < HID; k++)
        f = fmaf(__shfl_sync(0xffffffffu, h, k), sW[k * HID + lane], f);

    g_f[(size_t)n * HID + lane] = f;
    g_acc0[(size_t)n * HID + lane] = 0.f;
    if (lane < HEADS) g_den0[n * HEADS + lane] = 0.f;

    // el/er per head: segmented 8-lane reductions
    float pl = f * __ldg(al + lane);
    float pr = f * __ldg(ar + lane);
    pl += __shfl_xor_sync(0xffffffffu, pl, 1);
    pr += __shfl_xor_sync(0xffffffffu, pr, 1);
    pl += __shfl_xor_sync(0xffffffffu, pl, 2);
    pr += __shfl_xor_sync(0xffffffffu, pr, 2);
    pl += __shfl_xor_sync(0xffffffffu, pl, 4);
    pr += __shfl_xor_sync(0xffffffffu, pr, 4);
    if ((lane & 7) == 0) {
        g_el[n * HEADS + (lane >> 3)] = pl;
        g_er[n * HEADS + (lane >> 3)] = pr;
    }
}

// ---------------- K1/K3: edge pass, 32 edges per warp batch (round-2 proven engine) ----------------
// Phase A (1 edge/lane): coalesced src/dst, float4 gather el[s]/er[d], exp for
// all 4 heads, vector RED for den. Phase B (8 rounds x 4 edges, 8 lanes/edge):
// LDG.128 f[src], red.v4 acc[dst]. Softmax max-pass elided (shift-invariant;
// |e|=O(0.05)) — validated rounds 1-7.
__global__ void __launch_bounds__(256, 8) k_edge(
        const int* __restrict__ src, const int* __restrict__ dst,
        float* __restrict__ acc, float* __restrict__ den) {
    int lane = threadIdx.x & 31;
    int warp = (blockIdx.x * blockDim.x + threadIdx.x) >> 5;
    int nwarp = (gridDim.x * blockDim.x) >> 5;
    int sub = lane & 7;       // float4 slot within a 32-float row
    int head = sub >> 1;      // head of this float4 slot
    const float4* f4 = (const float4*)g_f;
    const float4* el4 = (const float4*)g_el;
    const float4* er4 = (const float4*)g_er;

    for (int base = warp * 32; base < N_EDGES; base += nwarp * 32) {
        int e = base + lane;                      // N_EDGES % 32 == 0
        int s = __ldg(src + e);
        int d = __ldg(dst + e);
        float4 el = __ldg(el4 + s);
        float4 er = __ldg(er4 + d);
        float4 x = make_float4(el.x + er.x, el.y + er.y, el.z + er.z, el.w + er.w);
        x.x = x.x > 0.f ? x.x : 0.2f * x.x;
        x.y = x.y > 0.f ? x.y : 0.2f * x.y;
        x.z = x.z > 0.f ? x.z : 0.2f * x.z;
        x.w = x.w > 0.f ? x.w : 0.2f * x.w;
        float4 ex = make_float4(__expf(x.x), __expf(x.y), __expf(x.z), __expf(x.w));
        red_add_v4(den + d * HEADS, ex);          // all 4 heads, one vector RED

#pragma unroll
        for (int r = 0; r < 8; r++) {
            int idx = r * 4 + (lane >> 3);        // which of the 32 edges this group serves
            int s_r = __shfl_sync(0xffffffffu, s, idx);
            int d_r = __shfl_sync(0xffffffffu, d, idx);
            float c0 = __shfl_sync(0xffffffffu, ex.x, idx);
            float c1 = __shfl_sync(0xffffffffu, ex.y, idx);
            float c2 = __shfl_sync(0xffffffffu, ex.z, idx);
            float c3 = __shfl_sync(0xffffffffu, ex.w, idx);
            float exv = head == 0 ? c0 : head == 1 ? c1 : head == 2 ? c2 : c3;
            float4 fv = __ldg(f4 + s_r * 8 + sub);
            float4 p = make_float4(exv * fv.x, exv * fv.y, exv * fv.z, exv * fv.w);
            red_add_v4(acc + d_r * 32 + sub * 4, p);
        }
    }
}

// ---------------- K2: warp-per-node: h1 = relu(acc0/den0 + b0); f1 = h1@W1; el1/er1; zero acc1/den1/sums ----------------
__global__ void __launch_bounds__(256) k_node_mid(
        const float* __restrict__ b0,
        const float* __restrict__ W,
        const float* __restrict__ al,
        const float* __restrict__ ar) {
    __shared__ float sW[HID * HID];
    int tid = threadIdx.x;
    for (int i = tid; i < HID * HID; i += 256) sW[i] = W[i];
    int t = blockIdx.x * 256 + tid;
    if (t < N_GRAPHS * HID) g_sums[t] = 0.f;
    if (t < N_GRAPHS) g_cnt[t] = 0.f;
    __syncthreads();

    int n = t >> 5;
    int lane = tid & 31;
    if (n >= N_NODES) return;

    float dv = g_den0[n * HEADS + (lane >> 3)];
    float inv = dv > 0.f ? __fdividef(1.f, dv) : 0.f;
    float a = g_acc0[(size_t)n * HID + lane];
    float h = fmaxf(fmaf(a, inv, __ldg(b0 + lane)), 0.f);

    float f = 0.f;
#pragma unroll
    for (int k = 0; k < HID; k++)
        f = fmaf(__shfl_sync(0xffffffffu, h, k), sW[k * HID + lane], f);

    g_f[(size_t)n * HID + lane] = f;
    g_acc1[(size_t)n * HID + lane] = 0.f;
    if (lane < HEADS) g_den1[n * HEADS + lane] = 0.f;

    float pl = f * __ldg(al + lane);
    float pr = f * __ldg(ar + lane);
    pl += __shfl_xor_sync(0xffffffffu, pl, 1);
    pr += __shfl_xor_sync(0xffffffffu, pr, 1);
    pl += __shfl_xor_sync(0xffffffffu, pl, 2);
    pr += __shfl_xor_sync(0xffffffffu, pr, 2);
    pl += __shfl_xor_sync(0xffffffffu, pl, 4);
    pr += __shfl_xor_sync(0xffffffffu, pr, 4);
    if ((lane & 7) == 0) {
        g_el[n * HEADS + (lane >> 3)] = pl;
        g_er[n * HEADS + (lane >> 3)] = pr;
    }
}

// ---------------- K4: h2 + run-length pooled per-graph sums (graph_ids sorted) ----------------
__global__ void k_pool(const int* __restrict__ graph_ids,
                       const float* __restrict__ b1) {
    int lane = threadIdx.x & 31;
    int warp = (blockIdx.x * blockDim.x + threadIdx.x) >> 5;
    int nwarp = (gridDim.x * blockDim.x) >> 5;
    int head = lane >> 3;
    float bl = __ldg(b1 + lane);
    int nchunk = (N_NODES + 31) / 32;
    for (int c = warp; c < nchunk; c += nwarp) {
        int base = c * 32;
        int lim = min(32, N_NODES - base);
        float runsum = 0.f;
        int rung = __ldg(graph_ids + base);
        int runcnt = 0;
        for (int i = 0; i < lim; i++) {
            int n = base + i;
            int gid = __ldg(graph_ids + n);            // uniform across warp
            float dv = g_den1[n * HEADS + head];
            float v  = g_acc1[(size_t)n * HID + lane];
            float hv = dv > 0.f ? __fdividef(v, dv) : 0.f;
            hv = fmaxf(hv + bl, 0.f);
            if (gid != rung) {
                atomicAdd(g_sums + rung * HID + lane, runsum);
                if (lane == 0) atomicAdd(g_cnt + rung, (float)runcnt);
                runsum = 0.f; runcnt = 0; rung = gid;
            }
            runsum += hv; runcnt++;
        }
        atomicAdd(g_sums + rung * HID + lane, runsum);
        if (lane == 0) atomicAdd(g_cnt + rung, (float)runcnt);
    }
}

// ---------------- K5: scorer MLP ----------------
__global__ void k_score(const float* __restrict__ sw1, const float* __restrict__ sb1,
                        const float* __restrict__ sw2, const float* __restrict__ sb2,
                        float* __restrict__ out) {
    __shared__ float s1[HID * HID];
    __shared__ float sb[HID], s2[HID];
    int t = threadIdx.x;
    for (int i = t; i < HID * HID; i += blockDim.x) s1[i] = sw1[i];
    if (t < HID) { sb[t] = sb1[t]; s2[t] = sw2[t]; }
    __syncthreads();
    if (t < N_GRAPHS) {
        float c = fmaxf(g_cnt[t], 1.f);
        float invc = __fdividef(1.f, c);
        float hg[HID];
#pragma unroll
        for (int k = 0; k < HID; k++) hg[k] = g_sums[t * HID + k] * invc;
        float score = __ldg(sb2);
#pragma unroll
        for (int j = 0; j < HID; j++) {
            float a = sb[j];
#pragma unroll
            for (int k = 0; k < HID; k++) a += hg[k] * s1[k * HID + j];
            a = fmaxf(a, 0.f);
            score += a * s2[j];
        }
        out[t] = score;
    }
}

// ---------------- launch ----------------
extern "C" void kernel_launch(void* const* d_in, const int* in_sizes, int n_in,
                              void* d_out, int out_size) {
    const int*   node_ids = (const int*)d_in[0];
    const int*   src      = (const int*)d_in[1];
    const int*   dst      = (const int*)d_in[2];
    const int*   gids     = (const int*)d_in[3];
    const float* emb      = (const float*)d_in[4];
    const float* W0       = (const float*)d_in[5];
    const float* al0      = (const float*)d_in[6];
    const float* ar0      = (const float*)d_in[7];
    const float* b0       = (const float*)d_in[8];
    const float* W1       = (const float*)d_in[9];
    const float* al1      = (const float*)d_in[10];
    const float* ar1      = (const float*)d_in[11];
    const float* b1       = (const float*)d_in[12];
    const float* sw1      = (const float*)d_in[13];
    const float* sb1      = (const float*)d_in[14];
    const float* sw2      = (const float*)d_in[15];
    const float* sb2      = (const float*)d_in[16];
    float* out = (float*)d_out;

    void *acc0, *den0, *acc1, *den1;
    cudaGetSymbolAddress(&acc0, g_acc0);
    cudaGetSymbolAddress(&den0, g_den0);
    cudaGetSymbolAddress(&acc1, g_acc1);
    cudaGetSymbolAddress(&den1, g_den1);

    const int nodeWarpBlocks = (N_NODES * 32 + 255) / 256;   // warp per node

    k_gather_fc<<<nodeWarpBlocks, 256>>>(node_ids, emb, W0, al0, ar0);
    k_edge<<<2048, 256>>>(src, dst, (float*)acc0, (float*)den0);
    k_node_mid<<<nodeWarpBlocks, 256>>>(b0, W1, al1, ar1);
    k_edge<<<2048, 256>>>(src, dst, (float*)acc1, (float*)den1);
    k_pool<<<(6250 + 7) / 8, 256>>>(gids, b1);
    k_score<<<1, 64>>>(sw1, sb1, sw2, sb2, out);
}

// round 9
// speedup vs baseline: 1.2205x; 1.2205x over previous
#include <cuda_runtime.h>
#include <cstddef>

#define N_NODES 200000
#define N_EDGES 3200000
#define N_GRAPHS 64
#define HID 32
#define HEADS 4

// ---------------- scratch (device globals; no allocation allowed) ----------------
__device__ float g_f[(size_t)N_NODES * HID];      // fc features (both layers)
__device__ float g_er[(size_t)N_NODES * HEADS];   // per-head er
__device__ float g_acc0[(size_t)N_NODES * HID];
__device__ float g_den0[(size_t)N_NODES * 8];     // den, x2-duplicated per head (slot=sub)
__device__ float g_acc1[(size_t)N_NODES * HID];
__device__ float g_den1[(size_t)N_NODES * 8];
__device__ float g_sums[N_GRAPHS * HID];
__device__ float g_cnt[N_GRAPHS];

__device__ __forceinline__ void red_add_v4(float* addr, float4 v) {
    asm volatile("red.global.add.v4.f32 [%0], {%1,%2,%3,%4};"
                 :: "l"(addr), "f"(v.x), "f"(v.y), "f"(v.z), "f"(v.w)
                 : "memory");
}
__device__ __forceinline__ void red_add_f(float* addr, float v) {
    asm volatile("red.global.add.f32 [%0], %1;" :: "l"(addr), "f"(v) : "memory");
}

// ---------------- K0: thread-per-node, chunked: h = emb[node_ids]; f = h@W0; er; zero acc0/den0 ----------------
// f computed in 4 chunks of 8 outputs (chunk == head) so f[32] never lives in
// registers: regs ~52 vs 69 (round-4 profile: occ 31% was the node bottleneck).
__global__ void __launch_bounds__(128) k_gather_fc(
        const int* __restrict__ node_ids,
        const float* __restrict__ emb,
        const float* __restrict__ W,
        const float* __restrict__ ar) {
    __shared__ float sW[HID * HID];
    __shared__ float sar[HID];
    int tid = threadIdx.x;
    for (int i = tid; i < HID * HID; i += 128) sW[i] = W[i];
    if (tid < HID) sar[tid] = ar[tid];
    __syncthreads();

    int n = blockIdx.x * 128 + tid;
    if (n >= N_NODES) return;

    int nid = __ldg(node_ids + n);
    const float4* hrow = (const float4*)(emb + (size_t)nid * HID);
    float h[HID];
#pragma unroll
    for (int i = 0; i < 8; i++) {
        float4 v = __ldg(hrow + i);
        h[4 * i] = v.x; h[4 * i + 1] = v.y; h[4 * i + 2] = v.z; h[4 * i + 3] = v.w;
    }
    float4* fout = (float4*)(g_f + (size_t)n * HID);
    float4* aout = (float4*)(g_acc0 + (size_t)n * HID);
    const float4 z4 = make_float4(0.f, 0.f, 0.f, 0.f);
#pragma unroll
    for (int c = 0; c < 4; c++) {                 // chunk c = head c (outputs 8c..8c+7)
        float f[8];
#pragma unroll
        for (int j = 0; j < 8; j++) f[j] = 0.f;
#pragma unroll
        for (int k = 0; k < HID; k++) {
            float hk = h[k];
            const float* wr = sW + k * HID + c * 8;
#pragma unroll
            for (int j = 0; j < 8; j++) f[j] = fmaf(hk, wr[j], f[j]);
        }
        fout[2 * c]     = make_float4(f[0], f[1], f[2], f[3]);
        fout[2 * c + 1] = make_float4(f[4], f[5], f[6], f[7]);
        aout[2 * c] = z4; aout[2 * c + 1] = z4;
        float er = 0.f;
#pragma unroll
        for (int j = 0; j < 8; j++) er = fmaf(f[j], sar[c * 8 + j], er);
        g_er[n * HEADS + c] = er;
    }
    ((float4*)g_den0)[n * 2] = z4;
    ((float4*)g_den0)[n * 2 + 1] = z4;
}

// ---------------- K1/K3: edge pass — 4-wf/edge, minimal shuffles, occ-capped ----------------
// Phase A: coalesced src/dst only. Phase B (8 rounds x 4 edges, 8 lanes/edge):
// er via direct per-lane ldg (1 wf), f via LDG.128 (1 wf), el recomputed from f
// (dot + 1 shfl_xor), acc red.v4 (1 wf), den per-lane scalar red into
// x2-duplicated slots (1 wf, no shuffles). Softmax max-pass elided
// (shift-invariant; |e|=O(0.05)) — validated rounds 1-8.
__global__ void __launch_bounds__(256, 8) k_edge(
        const int* __restrict__ src, const int* __restrict__ dst,
        const float* __restrict__ al,
        float* __restrict__ acc, float* __restrict__ den) {
    int lane = threadIdx.x & 31;
    int warp = (blockIdx.x * blockDim.x + threadIdx.x) >> 5;
    int nwarp = (gridDim.x * blockDim.x) >> 5;
    int sub = lane & 7;       // float4 slot within the 32-float row
    int grp = lane >> 3;      // which of the 4 edges this lane serves
    int head = sub >> 1;      // head of this slot
    const float4* f4 = (const float4*)g_f;
    float4 sal = __ldg(((const float4*)al) + sub);

    for (int base = warp * 32; base < N_EDGES; base += nwarp * 32) {
        int e = base + lane;                      // N_EDGES % 32 == 0
        int s = __ldg(src + e);
        int d = __ldg(dst + e);

#pragma unroll
        for (int r = 0; r < 8; r++) {
            int idx = r * 4 + grp;
            int s_r = __shfl_sync(0xffffffffu, s, idx);
            int d_r = __shfl_sync(0xffffffffu, d, idx);

            float er_h = __ldg(g_er + d_r * HEADS + head);      // 8 lanes, 1 line
            float4 fv = __ldg(f4 + s_r * 8 + sub);              // 128B row, 1 wf
            float part = fv.x * sal.x + fv.y * sal.y + fv.z * sal.z + fv.w * sal.w;
            float el_h = part + __shfl_xor_sync(0xffffffffu, part, 1);

            float x = el_h + er_h;
            x = x > 0.f ? x : 0.2f * x;           // leaky_relu(0.2)
            float ex = __expf(x);

            red_add_v4(acc + d_r * 32 + sub * 4,
                       make_float4(ex * fv.x, ex * fv.y, ex * fv.z, ex * fv.w));
            red_add_f(den + d_r * 8 + sub, ex);   // own slot, no shuffles
        }
    }
}

// ---------------- K2: thread-per-node, chunked: h1 = relu(acc0/den0+b0); f1 = h1@W1; er1; zero acc1/den1/sums ----------------
__global__ void __launch_bounds__(128) k_node_mid(
        const float* __restrict__ b0,
        const float* __restrict__ W,
        const float* __restrict__ ar) {
    __shared__ float sW[HID * HID];
    __shared__ float sar[HID], sb[HID];
    int tid = threadIdx.x;
    for (int i = tid; i < HID * HID; i += 128) sW[i] = W[i];
    if (tid < HID) { sar[tid] = ar[tid]; sb[tid] = b0[tid]; }
    __syncthreads();

    int n = blockIdx.x * 128 + tid;
    if (n < N_GRAPHS * HID) g_sums[n] = 0.f;
    if (n < N_GRAPHS) g_cnt[n] = 0.f;
    if (n >= N_NODES) return;

    float h[HID];
    const float4* arow = (const float4*)(g_acc0 + (size_t)n * HID);
#pragma unroll
    for (int hh = 0; hh < HEADS; hh++) {
        float dv = g_den0[(size_t)n * 8 + 2 * hh];
        float inv = dv > 0.f ? __fdividef(1.f, dv) : 0.f;
        float4 v0 = arow[2 * hh];
        float4 v1 = arow[2 * hh + 1];
        h[8 * hh]     = fmaxf(fmaf(v0.x, inv, sb[8 * hh]),     0.f);
        h[8 * hh + 1] = fmaxf(fmaf(v0.y, inv, sb[8 * hh + 1]), 0.f);
        h[8 * hh + 2] = fmaxf(fmaf(v0.z, inv, sb[8 * hh + 2]), 0.f);
        h[8 * hh + 3] = fmaxf(fmaf(v0.w, inv, sb[8 * hh + 3]), 0.f);
        h[8 * hh + 4] = fmaxf(fmaf(v1.x, inv, sb[8 * hh + 4]), 0.f);
        h[8 * hh + 5] = fmaxf(fmaf(v1.y, inv, sb[8 * hh + 5]), 0.f);
        h[8 * hh + 6] = fmaxf(fmaf(v1.z, inv, sb[8 * hh + 6]), 0.f);
        h[8 * hh + 7] = fmaxf(fmaf(v1.w, inv, sb[8 * hh + 7]), 0.f);
    }

    float4* fout = (float4*)(g_f + (size_t)n * HID);
    float4* aout = (float4*)(g_acc1 + (size_t)n * HID);
    const float4 z4 = make_float4(0.f, 0.f, 0.f, 0.f);
#pragma unroll
    for (int c = 0; c < 4; c++) {
        float f[8];
#pragma unroll
        for (int j = 0; j < 8; j++) f[j] = 0.f;
#pragma unroll
        for (int k = 0; k < HID; k++) {
            float hk = h[k];
            const float* wr = sW + k * HID + c * 8;
#pragma unroll
            for (int j = 0; j < 8; j++) f[j] = fmaf(hk, wr[j], f[j]);
        }
        fout[2 * c]     = make_float4(f[0], f[1], f[2], f[3]);
        fout[2 * c + 1] = make_float4(f[4], f[5], f[6], f[7]);
        aout[2 * c] = z4; aout[2 * c + 1] = z4;
        float er = 0.f;
#pragma unroll
        for (int j = 0; j < 8; j++) er = fmaf(f[j], sar[c * 8 + j], er);
        g_er[n * HEADS + c] = er;
    }
    ((float4*)g_den1)[n * 2] = z4;
    ((float4*)g_den1)[n * 2 + 1] = z4;
}

// ---------------- K4: h2 + run-length pooled per-graph sums (graph_ids sorted) ----------------
__global__ void k_pool(const int* __restrict__ graph_ids,
                       const float* __restrict__ b1) {
    int lane = threadIdx.x & 31;
    int warp = (blockIdx.x * blockDim.x + threadIdx.x) >> 5;
    int nwarp = (gridDim.x * blockDim.x) >> 5;
    int dslot = (lane >> 3) << 1;
    float bl = __ldg(b1 + lane);
    int nchunk = (N_NODES + 31) / 32;
    for (int c = warp; c < nchunk; c += nwarp) {
        int base = c * 32;
        int lim = min(32, N_NODES - base);
        float runsum = 0.f;
        int rung = __ldg(graph_ids + base);
        int runcnt = 0;
        for (int i = 0; i < lim; i++) {
            int n = base + i;
            int gid = __ldg(graph_ids + n);            // uniform across warp
            float dv = g_den1[(size_t)n * 8 + dslot];
            float v  = g_acc1[(size_t)n * HID + lane];
            float hv = dv > 0.f ? __fdividef(v, dv) : 0.f;
            hv = fmaxf(hv + bl, 0.f);
            if (gid != rung) {
                atomicAdd(g_sums + rung * HID + lane, runsum);
                if (lane == 0) atomicAdd(g_cnt + rung, (float)runcnt);
                runsum = 0.f; runcnt = 0; rung = gid;
            }
            runsum += hv; runcnt++;
        }
        atomicAdd(g_sums + rung * HID + lane, runsum);
        if (lane == 0) atomicAdd(g_cnt + rung, (float)runcnt);
    }
}

// ---------------- K5: scorer MLP ----------------
__global__ void k_score(const float* __restrict__ sw1, const float* __restrict__ sb1,
                        const float* __restrict__ sw2, const float* __restrict__ sb2,
                        float* __restrict__ out) {
    __shared__ float s1[HID * HID];
    __shared__ float sb[HID], s2[HID];
    int t = threadIdx.x;
    for (int i = t; i < HID * HID; i += blockDim.x) s1[i] = sw1[i];
    if (t < HID) { sb[t] = sb1[t]; s2[t] = sw2[t]; }
    __syncthreads();
    if (t < N_GRAPHS) {
        float c = fmaxf(g_cnt[t], 1.f);
        float invc = __fdividef(1.f, c);
        float hg[HID];
#pragma unroll
        for (int k = 0; k < HID; k++) hg[k] = g_sums[t * HID + k] * invc;
        float score = __ldg(sb2);
#pragma unroll
        for (int j = 0; j < HID; j++) {
            float a = sb[j];
#pragma unroll
            for (int k = 0; k < HID; k++) a += hg[k] * s1[k * HID + j];
            a = fmaxf(a, 0.f);
            score += a * s2[j];
        }
        out[t] = score;
    }
}

// ---------------- launch ----------------
extern "C" void kernel_launch(void* const* d_in, const int* in_sizes, int n_in,
                              void* d_out, int out_size) {
    const int*   node_ids = (const int*)d_in[0];
    const int*   src      = (const int*)d_in[1];
    const int*   dst      = (const int*)d_in[2];
    const int*   gids     = (const int*)d_in[3];
    const float* emb      = (const float*)d_in[4];
    const float* W0       = (const float*)d_in[5];
    const float* al0      = (const float*)d_in[6];
    const float* ar0      = (const float*)d_in[7];
    const float* b0       = (const float*)d_in[8];
    const float* W1       = (const float*)d_in[9];
    const float* al1      = (const float*)d_in[10];
    const float* ar1      = (const float*)d_in[11];
    const float* b1       = (const float*)d_in[12];
    const float* sw1      = (const float*)d_in[13];
    const float* sb1      = (const float*)d_in[14];
    const float* sw2      = (const float*)d_in[15];
    const float* sb2      = (const float*)d_in[16];
    float* out = (float*)d_out;

    void *acc0, *den0, *acc1, *den1;
    cudaGetSymbolAddress(&acc0, g_acc0);
    cudaGetSymbolAddress(&den0, g_den0);
    cudaGetSymbolAddress(&acc1, g_acc1);
    cudaGetSymbolAddress(&den1, g_den1);

    const int nodeBlocks = (N_NODES + 127) / 128;

    k_gather_fc<<<nodeBlocks, 128>>>(node_ids, emb, W0, ar0);
    k_edge<<<2048, 256>>>(src, dst, al0, (float*)acc0, (float*)den0);
    k_node_mid<<<nodeBlocks, 128>>>(b0, W1, ar1);
    k_edge<<<2048, 256>>>(src, dst, al1, (float*)acc1, (float*)den1);
    k_pool<<<(6250 + 7) / 8, 256>>>(gids, b1);
    k_score<<<1, 64>>>(sw1, sb1, sw2, sb2, out);
}

// round 10
// speedup vs baseline: 1.2251x; 1.0037x over previous
#include <cuda_runtime.h>
#include <cstddef>

#define N_NODES 200000
#define N_EDGES 3200000
#define N_GRAPHS 64
#define HID 32
#define HEADS 4

// ---------------- scratch (device globals; no allocation allowed) ----------------
__device__ float g_f[(size_t)N_NODES * HID];      // fc features (both layers)
__device__ float g_er[(size_t)N_NODES * HEADS];   // per-head er
__device__ float g_acc0[(size_t)N_NODES * HID];
__device__ float g_den0[(size_t)N_NODES * 8];     // den, x2-duplicated per head (slot=sub)
__device__ float g_acc1[(size_t)N_NODES * HID];
__device__ float g_den1[(size_t)N_NODES * 8];
__device__ float g_sums[N_GRAPHS * HID];
__device__ float g_cnt[N_GRAPHS];

__device__ __forceinline__ void red_add_v4(float* addr, float4 v) {
    asm volatile("red.global.add.v4.f32 [%0], {%1,%2,%3,%4};"
                 :: "l"(addr), "f"(v.x), "f"(v.y), "f"(v.z), "f"(v.w)
                 : "memory");
}
__device__ __forceinline__ void red_add_f(float* addr, float v) {
    asm volatile("red.global.add.f32 [%0], %1;" :: "l"(addr), "f"(v) : "memory");
}

// ---------------- K0: thread-per-node, chunked: h = emb[node_ids]; f = h@W0; er; zero acc0/den0 ----------------
// f computed in 4 chunks of 8 outputs (chunk == head) so f[32] never lives in
// registers: regs ~52 vs 69 (round-4 profile: occ 31% was the node bottleneck).
__global__ void __launch_bounds__(128) k_gather_fc(
        const int* __restrict__ node_ids,
        const float* __restrict__ emb,
        const float* __restrict__ W,
        const float* __restrict__ ar) {
    __shared__ float sW[HID * HID];
    __shared__ float sar[HID];
    int tid = threadIdx.x;
    for (int i = tid; i < HID * HID; i += 128) sW[i] = W[i];
    if (tid < HID) sar[tid] = ar[tid];
    __syncthreads();

    int n = blockIdx.x * 128 + tid;
    if (n >= N_NODES) return;

    int nid = __ldg(node_ids + n);
    const float4* hrow = (const float4*)(emb + (size_t)nid * HID);
    float h[HID];
#pragma unroll
    for (int i = 0; i < 8; i++) {
        float4 v = __ldg(hrow + i);
        h[4 * i] = v.x; h[4 * i + 1] = v.y; h[4 * i + 2] = v.z; h[4 * i + 3] = v.w;
    }
    float4* fout = (float4*)(g_f + (size_t)n * HID);
    float4* aout = (float4*)(g_acc0 + (size_t)n * HID);
    const float4 z4 = make_float4(0.f, 0.f, 0.f, 0.f);
#pragma unroll
    for (int c = 0; c < 4; c++) {                 // chunk c = head c (outputs 8c..8c+7)
        float f[8];
#pragma unroll
        for (int j = 0; j < 8; j++) f[j] = 0.f;
#pragma unroll
        for (int k = 0; k < HID; k++) {
            float hk = h[k];
            const float* wr = sW + k * HID + c * 8;
#pragma unroll
            for (int j = 0; j < 8; j++) f[j] = fmaf(hk, wr[j], f[j]);
        }
        fout[2 * c]     = make_float4(f[0], f[1], f[2], f[3]);
        fout[2 * c + 1] = make_float4(f[4], f[5], f[6], f[7]);
        aout[2 * c] = z4; aout[2 * c + 1] = z4;
        float er = 0.f;
#pragma unroll
        for (int j = 0; j < 8; j++) er = fmaf(f[j], sar[c * 8 + j], er);
        g_er[n * HEADS + c] = er;
    }
    ((float4*)g_den0)[n * 2] = z4;
    ((float4*)g_den0)[n * 2 + 1] = z4;
}

// ---------------- K1/K3: edge pass — 4-wf/edge, minimal shuffles, occ-capped ----------------
// Phase A: coalesced src/dst only. Phase B (8 rounds x 4 edges, 8 lanes/edge):
// er via direct per-lane ldg (1 wf), f via LDG.128 (1 wf), el recomputed from f
// (dot + 1 shfl_xor), acc red.v4 (1 wf), den per-lane scalar red into
// x2-duplicated slots (1 wf, no shuffles). Softmax max-pass elided
// (shift-invariant; |e|=O(0.05)) — validated rounds 1-8.
__global__ void __launch_bounds__(256, 8) k_edge(
        const int* __restrict__ src, const int* __restrict__ dst,
        const float* __restrict__ al,
        float* __restrict__ acc, float* __restrict__ den) {
    int lane = threadIdx.x & 31;
    int warp = (blockIdx.x * blockDim.x + threadIdx.x) >> 5;
    int nwarp = (gridDim.x * blockDim.x) >> 5;
    int sub = lane & 7;       // float4 slot within the 32-float row
    int grp = lane >> 3;      // which of the 4 edges this lane serves
    int head = sub >> 1;      // head of this slot
    const float4* f4 = (const float4*)g_f;
    float4 sal = __ldg(((const float4*)al) + sub);

    for (int base = warp * 32; base < N_EDGES; base += nwarp * 32) {
        int e = base + lane;                      // N_EDGES % 32 == 0
        int s = __ldg(src + e);
        int d = __ldg(dst + e);

#pragma unroll
        for (int r = 0; r < 8; r++) {
            int idx = r * 4 + grp;
            int s_r = __shfl_sync(0xffffffffu, s, idx);
            int d_r = __shfl_sync(0xffffffffu, d, idx);

            float er_h = __ldg(g_er + d_r * HEADS + head);      // 8 lanes, 1 line
            float4 fv = __ldg(f4 + s_r * 8 + sub);              // 128B row, 1 wf
            float part = fv.x * sal.x + fv.y * sal.y + fv.z * sal.z + fv.w * sal.w;
            float el_h = part + __shfl_xor_sync(0xffffffffu, part, 1);

            float x = el_h + er_h;
            x = x > 0.f ? x : 0.2f * x;           // leaky_relu(0.2)
            float ex = __expf(x);

            red_add_v4(acc + d_r * 32 + sub * 4,
                       make_float4(ex * fv.x, ex * fv.y, ex * fv.z, ex * fv.w));
            red_add_f(den + d_r * 8 + sub, ex);   // own slot, no shuffles
        }
    }
}

// ---------------- K2: thread-per-node, chunked: h1 = relu(acc0/den0+b0); f1 = h1@W1; er1; zero acc1/den1/sums ----------------
__global__ void __launch_bounds__(128) k_node_mid(
        const float* __restrict__ b0,
        const float* __restrict__ W,
        const float* __restrict__ ar) {
    __shared__ float sW[HID * HID];
    __shared__ float sar[HID], sb[HID];
    int tid = threadIdx.x;
    for (int i = tid; i < HID * HID; i += 128) sW[i] = W[i];
    if (tid < HID) { sar[tid] = ar[tid]; sb[tid] = b0[tid]; }
    __syncthreads();

    int n = blockIdx.x * 128 + tid;
    if (n < N_GRAPHS * HID) g_sums[n] = 0.f;
    if (n < N_GRAPHS) g_cnt[n] = 0.f;
    if (n >= N_NODES) return;

    float h[HID];
    const float4* arow = (const float4*)(g_acc0 + (size_t)n * HID);
#pragma unroll
    for (int hh = 0; hh < HEADS; hh++) {
        float dv = g_den0[(size_t)n * 8 + 2 * hh];
        float inv = dv > 0.f ? __fdividef(1.f, dv) : 0.f;
        float4 v0 = arow[2 * hh];
        float4 v1 = arow[2 * hh + 1];
        h[8 * hh]     = fmaxf(fmaf(v0.x, inv, sb[8 * hh]),     0.f);
        h[8 * hh + 1] = fmaxf(fmaf(v0.y, inv, sb[8 * hh + 1]), 0.f);
        h[8 * hh + 2] = fmaxf(fmaf(v0.z, inv, sb[8 * hh + 2]), 0.f);
        h[8 * hh + 3] = fmaxf(fmaf(v0.w, inv, sb[8 * hh + 3]), 0.f);
        h[8 * hh + 4] = fmaxf(fmaf(v1.x, inv, sb[8 * hh + 4]), 0.f);
        h[8 * hh + 5] = fmaxf(fmaf(v1.y, inv, sb[8 * hh + 5]), 0.f);
        h[8 * hh + 6] = fmaxf(fmaf(v1.z, inv, sb[8 * hh + 6]), 0.f);
        h[8 * hh + 7] = fmaxf(fmaf(v1.w, inv, sb[8 * hh + 7]), 0.f);
    }

    float4* fout = (float4*)(g_f + (size_t)n * HID);
    float4* aout = (float4*)(g_acc1 + (size_t)n * HID);
    const float4 z4 = make_float4(0.f, 0.f, 0.f, 0.f);
#pragma unroll
    for (int c = 0; c < 4; c++) {
        float f[8];
#pragma unroll
        for (int j = 0; j < 8; j++) f[j] = 0.f;
#pragma unroll
        for (int k = 0; k < HID; k++) {
            float hk = h[k];
            const float* wr = sW + k * HID + c * 8;
#pragma unroll
            for (int j = 0; j < 8; j++) f[j] = fmaf(hk, wr[j], f[j]);
        }
        fout[2 * c]     = make_float4(f[0], f[1], f[2], f[3]);
        fout[2 * c + 1] = make_float4(f[4], f[5], f[6], f[7]);
        aout[2 * c] = z4; aout[2 * c + 1] = z4;
        float er = 0.f;
#pragma unroll
        for (int j = 0; j < 8; j++) er = fmaf(f[j], sar[c * 8 + j], er);
        g_er[n * HEADS + c] = er;
    }
    ((float4*)g_den1)[n * 2] = z4;
    ((float4*)g_den1)[n * 2 + 1] = z4;
}

// ---------------- K4: h2 + run-length pooled per-graph sums (graph_ids sorted) ----------------
__global__ void k_pool(const int* __restrict__ graph_ids,
                       const float* __restrict__ b1) {
    int lane = threadIdx.x & 31;
    int warp = (blockIdx.x * blockDim.x + threadIdx.x) >> 5;
    int nwarp = (gridDim.x * blockDim.x) >> 5;
    int dslot = (lane >> 3) << 1;
    float bl = __ldg(b1 + lane);
    int nchunk = (N_NODES + 31) / 32;
    for (int c = warp; c < nchunk; c += nwarp) {
        int base = c * 32;
        int lim = min(32, N_NODES - base);
        float runsum = 0.f;
        int rung = __ldg(graph_ids + base);
        int runcnt = 0;
        for (int i = 0; i < lim; i++) {
            int n = base + i;
            int gid = __ldg(graph_ids + n);            // uniform across warp
            float dv = g_den1[(size_t)n * 8 + dslot];
            float v  = g_acc1[(size_t)n * HID + lane];
            float hv = dv > 0.f ? __fdividef(v, dv) : 0.f;
            hv = fmaxf(hv + bl, 0.f);
            if (gid != rung) {
                atomicAdd(g_sums + rung * HID + lane, runsum);
                if (lane == 0) atomicAdd(g_cnt + rung, (float)runcnt);
                runsum = 0.f; runcnt = 0; rung = gid;
            }
            runsum += hv; runcnt++;
        }
        atomicAdd(g_sums + rung * HID + lane, runsum);
        if (lane == 0) atomicAdd(g_cnt + rung, (float)runcnt);
    }
}

// ---------------- K5: scorer MLP ----------------
__global__ void k_score(const float* __restrict__ sw1, const float* __restrict__ sb1,
                        const float* __restrict__ sw2, const float* __restrict__ sb2,
                        float* __restrict__ out) {
    __shared__ float s1[HID * HID];
    __shared__ float sb[HID], s2[HID];
    int t = threadIdx.x;
    for (int i = t; i < HID * HID; i += blockDim.x) s1[i] = sw1[i];
    if (t < HID) { sb[t] = sb1[t]; s2[t] = sw2[t]; }
    __syncthreads();
    if (t < N_GRAPHS) {
        float c = fmaxf(g_cnt[t], 1.f);
        float invc = __fdividef(1.f, c);
        float hg[HID];
#pragma unroll
        for (int k = 0; k < HID; k++) hg[k] = g_sums[t * HID + k] * invc;
        float score = __ldg(sb2);
#pragma unroll
        for (int j = 0; j < HID; j++) {
            float a = sb[j];
#pragma unroll
            for (int k = 0; k < HID; k++) a += hg[k] * s1[k * HID + j];
            a = fmaxf(a, 0.f);
            score += a * s2[j];
        }
        out[t] = score;
    }
}

// ---------------- launch ----------------
extern "C" void kernel_launch(void* const* d_in, const int* in_sizes, int n_in,
                              void* d_out, int out_size) {
    const int*   node_ids = (const int*)d_in[0];
    const int*   src      = (const int*)d_in[1];
    const int*   dst      = (const int*)d_in[2];
    const int*   gids     = (const int*)d_in[3];
    const float* emb      = (const float*)d_in[4];
    const float* W0       = (const float*)d_in[5];
    const float* al0      = (const float*)d_in[6];
    const float* ar0      = (const float*)d_in[7];
    const float* b0       = (const float*)d_in[8];
    const float* W1       = (const float*)d_in[9];
    const float* al1      = (const float*)d_in[10];
    const float* ar1      = (const float*)d_in[11];
    const float* b1       = (const float*)d_in[12];
    const float* sw1      = (const float*)d_in[13];
    const float* sb1      = (const float*)d_in[14];
    const float* sw2      = (const float*)d_in[15];
    const float* sb2      = (const float*)d_in[16];
    float* out = (float*)d_out;

    void *acc0, *den0, *acc1, *den1;
    cudaGetSymbolAddress(&acc0, g_acc0);
    cudaGetSymbolAddress(&den0, g_den0);
    cudaGetSymbolAddress(&acc1, g_acc1);
    cudaGetSymbolAddress(&den1, g_den1);

    const int nodeBlocks = (N_NODES + 127) / 128;

    k_gather_fc<<<nodeBlocks, 128>>>(node_ids, emb, W0, ar0);
    k_edge<<<2048, 256>>>(src, dst, al0, (float*)acc0, (float*)den0);
    k_node_mid<<<nodeBlocks, 128>>>(b0, W1, ar1);
    k_edge<<<2048, 256>>>(src, dst, al1, (float*)acc1, (float*)den1);
    k_pool<<<(6250 + 7) / 8, 256>>>(gids, b1);
    k_score<<<1, 64>>>(sw1, sb1, sw2, sb2, out);
}